// round 1
// baseline (speedup 1.0000x reference)
#include <cuda_runtime.h>

// Problem constants
#define B_   16
#define K_   64
#define BK   1024
#define IN_  128
#define H0   192
#define H1   64
#define UNF  6
#define HS   (H0 + H1)        // 256 state size
#define L2E  1.4426950408889634f

// -------- device scratch (no allocations allowed) --------
__device__ float4 g_d0[H0 * H0];     // layer0 recurrent derived params {-sig*L2E, sig*mu*L2E, relu(w)*erev, relu(w)}
__device__ float4 g_d1[H1 * H1];     // layer1 recurrent derived params
__device__ float4 g_din1[H0 * H1];   // layer1 input derived params
__device__ float4 g_hc0[H0];         // per-h constants layer0: {gl*vleak, gl, 1/(relu(cm)+eps), gdiff*sqrt(dt)}
__device__ float4 g_hc1[H1];
__device__ float  g_A0n[B_ * H0];    // layer0 input current numerator (broadcast over K!)
__device__ float  g_A0d[B_ * H0];
__device__ float  g_s0[BK * H0];     // layer0 output state
__device__ float  g_s1[BK * H1];     // layer1 output state

__device__ __forceinline__ float ex2f(float x) {
    float r; asm("ex2.approx.f32 %0, %1;" : "=f"(r) : "f"(x)); return r;
}
__device__ __forceinline__ float rcpf(float x) {
    float r; asm("rcp.approx.f32 %0, %1;" : "=f"(r) : "f"(x)); return r;
}
__device__ __forceinline__ float relu_(float x) { return x > 0.f ? x : 0.f; }

// ---------------- precompute: derived params + layer0 input currents ----------------
// thread ranges:
//   [0, 36864)               -> g_d0
//   [36864, 40960)           -> g_d1
//   [40960, 53248)           -> g_din1
//   [53248, 53440)           -> g_hc0
//   [53440, 53504)           -> g_hc1
//   [53504, 56576)           -> g_A0n / g_A0d  (B*H0 = 3072, each loops IN=128)
__global__ void precompute_kernel(
    const float* __restrict__ x,
    const float* __restrict__ gleak0, const float* __restrict__ vleak0, const float* __restrict__ cm0,
    const float* __restrict__ iw0, const float* __restrict__ isig0, const float* __restrict__ imu0,
    const float* __restrict__ ierev0,
    const float* __restrict__ w0, const float* __restrict__ sig0, const float* __restrict__ mu0,
    const float* __restrict__ erev0, const float* __restrict__ gdiff0,
    const float* __restrict__ gleak1, const float* __restrict__ vleak1, const float* __restrict__ cm1,
    const float* __restrict__ iw1, const float* __restrict__ isig1, const float* __restrict__ imu1,
    const float* __restrict__ ierev1,
    const float* __restrict__ w1, const float* __restrict__ sig1, const float* __restrict__ mu1,
    const float* __restrict__ erev1, const float* __restrict__ gdiff1)
{
    int idx = blockIdx.x * blockDim.x + threadIdx.x;
    const float sdt = 0.40824829046386302f;  // sqrt(1/6)

    if (idx < H0 * H0) {
        float s = sig0[idx], m = mu0[idx], wv = relu_(w0[idx]);
        g_d0[idx] = make_float4(-s * L2E, s * m * L2E, wv * erev0[idx], wv);
        return;
    }
    idx -= H0 * H0;
    if (idx < H1 * H1) {
        float s = sig1[idx], m = mu1[idx], wv = relu_(w1[idx]);
        g_d1[idx] = make_float4(-s * L2E, s * m * L2E, wv * erev1[idx], wv);
        return;
    }
    idx -= H1 * H1;
    if (idx < H0 * H1) {
        float s = isig1[idx], m = imu1[idx], wv = relu_(iw1[idx]);
        g_din1[idx] = make_float4(-s * L2E, s * m * L2E, wv * ierev1[idx], wv);
        return;
    }
    idx -= H0 * H1;
    if (idx < H0) {
        float gl = relu_(gleak0[idx]);
        g_hc0[idx] = make_float4(gl * vleak0[idx], gl,
                                 1.0f / (relu_(cm0[idx]) + 1e-8f), gdiff0[idx] * sdt);
        return;
    }
    idx -= H0;
    if (idx < H1) {
        float gl = relu_(gleak1[idx]);
        g_hc1[idx] = make_float4(gl * vleak1[idx], gl,
                                 1.0f / (relu_(cm1[idx]) + 1e-8f), gdiff1[idx] * sdt);
        return;
    }
    idx -= H1;
    if (idx < B_ * H0) {
        int b = idx / H0, h = idx - b * H0;
        float an = 0.f, ad = 0.f;
        for (int i = 0; i < IN_; ++i) {
            int p = i * H0 + h;
            float xv = x[b * IN_ + i];
            // sigmoid(isig*(x-imu)) = 1/(1 + 2^(-L2E*isig*(x-imu)))
            float y = -isig0[p] * (xv - imu0[p]) * L2E;
            float sg = rcpf(1.f + ex2f(y));
            float a = relu_(iw0[p]) * sg;
            an = fmaf(a, ierev0[p], an);
            ad += a;
        }
        g_A0n[idx] = an;
        g_A0d[idx] = ad;
    }
}

// ---------------- layer 0: 6 unfold steps, one CTA per particle row ----------------
__global__ void __launch_bounds__(H0) layer0_kernel(
    const float* __restrict__ particles,
    const float* __restrict__ noise0,
    float* __restrict__ out_particles)   // points at d_out + 1024 (particles region)
{
    __shared__ float vsm[H0];
    const int bk = blockIdx.x;
    const int h  = threadIdx.x;
    const int b  = bk >> 6;   // K = 64

    vsm[h] = particles[bk * HS + h];
    const float4 hc = g_hc0[h];
    const float a0n = g_A0n[b * H0 + h];
    const float a0d = g_A0d[b * H0 + h];
    __syncthreads();

    for (int step = 0; step < UNF; ++step) {
        float accN = a0n, accD = a0d;
        #pragma unroll 8
        for (int i = 0; i < H0; ++i) {
            float4 p = g_d0[i * H0 + h];
            float y  = fmaf(p.x, vsm[i], p.y);     // -L2E * sig * (v - mu)
            float sg = rcpf(1.0f + ex2f(y));       // sigmoid
            accN = fmaf(p.z, sg, accN);
            accD = fmaf(p.w, sg, accD);
        }
        float v = vsm[h];
        float d = (hc.x + accN - (hc.y + accD) * v) * hc.z;
        float n = noise0[(step * BK + bk) * H0 + h];
        v = fmaf(d, (1.0f / 6.0f), fmaf(hc.w, n, v));
        __syncthreads();
        vsm[h] = v;
        __syncthreads();
    }
    float v = vsm[h];
    g_s0[bk * H0 + h]              = v;
    out_particles[bk * HS + h]     = v;
}

// ---------------- layer 1: input currents (from s0) hoisted, then 6 steps ----------------
__global__ void __launch_bounds__(H1) layer1_kernel(
    const float* __restrict__ particles,
    const float* __restrict__ noise1,
    float* __restrict__ out_particles)
{
    __shared__ float s0sm[H0];
    __shared__ float vsm[H1];
    const int bk = blockIdx.x;
    const int h  = threadIdx.x;

    for (int j = h; j < H0; j += H1) s0sm[j] = g_s0[bk * H0 + j];
    vsm[h] = particles[bk * HS + H0 + h];
    const float4 hc = g_hc1[h];
    __syncthreads();

    // input currents from s0 (constant across unfolds)
    float ain = 0.f, adn = 0.f;
    #pragma unroll 8
    for (int i = 0; i < H0; ++i) {
        float4 p = g_din1[i * H1 + h];
        float y  = fmaf(p.x, s0sm[i], p.y);
        float sg = rcpf(1.0f + ex2f(y));
        ain = fmaf(p.z, sg, ain);
        adn = fmaf(p.w, sg, adn);
    }

    for (int step = 0; step < UNF; ++step) {
        float accN = ain, accD = adn;
        #pragma unroll 8
        for (int i = 0; i < H1; ++i) {
            float4 p = g_d1[i * H1 + h];
            float y  = fmaf(p.x, vsm[i], p.y);
            float sg = rcpf(1.0f + ex2f(y));
            accN = fmaf(p.z, sg, accN);
            accD = fmaf(p.w, sg, accD);
        }
        float v = vsm[h];
        float d = (hc.x + accN - (hc.y + accD) * v) * hc.z;
        float n = noise1[(step * BK + bk) * H1 + h];
        v = fmaf(d, (1.0f / 6.0f), fmaf(hc.w, n, v));
        __syncthreads();
        vsm[h] = v;
        __syncthreads();
    }
    float v = vsm[h];
    g_s1[bk * H1 + h]                   = v;
    out_particles[bk * HS + H0 + h]     = v;
}

// ---------------- output: softmax-weighted particle mean + log_weights passthrough ----------------
__global__ void __launch_bounds__(H1) output_kernel(
    const float* __restrict__ log_weights,
    float* __restrict__ d_out)
{
    __shared__ float red[K_];
    __shared__ float wsm[K_];
    const int b = blockIdx.x;
    const int t = threadIdx.x;   // = k for softmax phase, = h for reduce phase (K_ == H1 == 64)

    float lw = log_weights[b * K_ + t];
    red[t] = lw; __syncthreads();
    for (int s = 32; s > 0; s >>= 1) {
        if (t < s) red[t] = fmaxf(red[t], red[t + s]);
        __syncthreads();
    }
    float mx = red[0]; __syncthreads();
    float e = __expf(lw - mx);
    red[t] = e; __syncthreads();
    for (int s = 32; s > 0; s >>= 1) {
        if (t < s) red[t] += red[t + s];
        __syncthreads();
    }
    float inv = 1.0f / red[0];
    wsm[t] = e * inv;
    __syncthreads();

    float acc = 0.f;
    #pragma unroll 8
    for (int k = 0; k < K_; ++k)
        acc = fmaf(wsm[k], g_s1[(b * K_ + k) * H1 + t], acc);

    d_out[b * H1 + t] = acc;                             // output [B, H1]
    d_out[B_ * H1 + BK * HS + b * K_ + t] = lw;          // log_weights passthrough
}

// ---------------- launch ----------------
extern "C" void kernel_launch(void* const* d_in, const int* in_sizes, int n_in,
                              void* d_out, int out_size)
{
    const float* x           = (const float*)d_in[0];
    const float* particles   = (const float*)d_in[1];
    const float* log_weights = (const float*)d_in[2];
    const float* noise0      = (const float*)d_in[3];
    const float* noise1      = (const float*)d_in[4];

    // layer 0 params: indices 5..16, layer 1 params: 17..28
    precompute_kernel<<<(36864 + 4096 + 12288 + 192 + 64 + 3072 + 255) / 256, 256>>>(
        x,
        (const float*)d_in[5],  (const float*)d_in[6],  (const float*)d_in[7],
        (const float*)d_in[8],  (const float*)d_in[9],  (const float*)d_in[10],
        (const float*)d_in[11],
        (const float*)d_in[12], (const float*)d_in[13], (const float*)d_in[14],
        (const float*)d_in[15], (const float*)d_in[16],
        (const float*)d_in[17], (const float*)d_in[18], (const float*)d_in[19],
        (const float*)d_in[20], (const float*)d_in[21], (const float*)d_in[22],
        (const float*)d_in[23],
        (const float*)d_in[24], (const float*)d_in[25], (const float*)d_in[26],
        (const float*)d_in[27], (const float*)d_in[28]);

    float* out = (float*)d_out;
    float* out_particles = out + B_ * H1;   // particles region starts after output [16,64]

    layer0_kernel<<<BK, H0>>>(particles, noise0, out_particles);
    layer1_kernel<<<BK, H1>>>(particles, noise1, out_particles);
    output_kernel<<<B_, H1>>>(log_weights, out);
}